// round 15
// baseline (speedup 1.0000x reference)
#include <cuda_runtime.h>
#include <cuda_bf16.h>
#include <cuda_fp16.h>
#include <math.h>
#include <cstdint>

#define HD       128
#define MAXN     50000
#define MAXN_PAD 50176            // 3136 * 16
#define MAXE     1600000
#define TILES    (MAXN_PAD / 16)  // 3136
#define KSTEPS   8

#define PREPB_THREADS (3 * KSTEPS * 16 * 32)   // 12288
#define PREPB_BLKS    (PREPB_THREADS / 256)    // 48
#define HIST_BLKS     1184
#define MMA_BLKS      (TILES / 16)             // 196

// Q pre-scale: 0.25 * log2(e); clamp bound: 5 * log2(e)
#define QSCALE 0.36067376022224085f
#define PCLAMP 7.213475204444817f

// ---------------------------------------------------------------------------
// Device scratch (allocation-free; zero-initialized at module load)
// ---------------------------------------------------------------------------
__device__ float g_Q[MAXN_PAD * HD];
// Interleaved K/V, fp16: g_KV[node*32 + l] = {K2(4l),K2(4l+2),V2(4l),V2(4l+2)}
__device__ uint4 g_KV[MAXN_PAD * 32];

__device__ uint4 g_Afrag_hi[TILES * KSTEPS * 32];
__device__ uint4 g_Afrag_lo[TILES * KSTEPS * 32];
__device__ uint4 g_Bfrag[3 * KSTEPS * 16 * 32];

// CSR sort scratch. g_cnt starts zero (module init) and is re-zeroed by
// scan_kernel each call, keeping the graph-replay invariant.
__device__ int g_cnt[MAXN];
__device__ int g_off[MAXN + 1];
__device__ int g_pos[MAXN];
__device__ int g_esrc[MAXE];

// ---------------------------------------------------------------------------
// Helpers
// ---------------------------------------------------------------------------
__device__ __forceinline__ void split2(float x, float y, uint32_t& hi, uint32_t& lo) {
    __nv_bfloat16 hx = __float2bfloat16(x);
    __nv_bfloat16 hy = __float2bfloat16(y);
    __nv_bfloat16 lx = __float2bfloat16(x - __bfloat162float(hx));
    __nv_bfloat16 ly = __float2bfloat16(y - __bfloat162float(hy));
    __nv_bfloat162 H(hx, hy), L(lx, ly);
    hi = *(uint32_t*)&H;
    lo = *(uint32_t*)&L;
}

#define MMA16816(c, a0, a1, a2, a3, b0, b1)                                  \
    asm volatile(                                                            \
        "mma.sync.aligned.m16n8k16.row.col.f32.bf16.bf16.f32 "              \
        "{%0,%1,%2,%3}, {%4,%5,%6,%7}, {%8,%9}, {%0,%1,%2,%3};"             \
        : "+f"((c)[0]), "+f"((c)[1]), "+f"((c)[2]), "+f"((c)[3])             \
        : "r"(a0), "r"(a1), "r"(a2), "r"(a3), "r"(b0), "r"(b1))

// ---------------------------------------------------------------------------
// K1: prep_A + prep_B + hist (independent block ranges)
// ---------------------------------------------------------------------------
__global__ void prep_hist_kernel(const float* __restrict__ h,
                                 const float* __restrict__ Wq,
                                 const float* __restrict__ Wk,
                                 const float* __restrict__ Wv,
                                 const int* __restrict__ dst,
                                 int n, int E) {
    const int b = blockIdx.x;
    const int tid = threadIdx.x;

    if (b < TILES) {
        int idx = b * 256 + tid;
        int lane = idx & 31;
        int s    = (idx >> 5) & 7;
        int t    = b;

        int r1 = t * 16 + (lane >> 2);
        int r2 = r1 + 8;
        int c0 = s * 16 + (lane & 3) * 2;

        float2 x00 = make_float2(0.f, 0.f), x10 = x00, x01 = x00, x11 = x00;
        if (r1 < n) {
            x00 = *(const float2*)&h[(size_t)r1 * HD + c0];
            x01 = *(const float2*)&h[(size_t)r1 * HD + c0 + 8];
        }
        if (r2 < n) {
            x10 = *(const float2*)&h[(size_t)r2 * HD + c0];
            x11 = *(const float2*)&h[(size_t)r2 * HD + c0 + 8];
        }

        uint4 hi, lo;
        split2(x00.x, x00.y, hi.x, lo.x);
        split2(x10.x, x10.y, hi.y, lo.y);
        split2(x01.x, x01.y, hi.z, lo.z);
        split2(x11.x, x11.y, hi.w, lo.w);

        g_Afrag_hi[idx] = hi;
        g_Afrag_lo[idx] = lo;
    } else if (b < TILES + PREPB_BLKS) {
        int idx = (b - TILES) * 256 + tid;
        int lane = idx & 31;
        int j    = (idx >> 5) & 15;
        int s    = (idx >> 9) & 7;
        int m    = idx >> 12;

        const float* W = (m == 0) ? Wq : (m == 1) ? Wk : Wv;
        int nn = j * 8 + (lane >> 2);
        int k0 = s * 16 + (lane & 3) * 2;

        float w00 = W[(size_t)(k0 + 0) * HD + nn];
        float w01 = W[(size_t)(k0 + 1) * HD + nn];
        float w10 = W[(size_t)(k0 + 8) * HD + nn];
        float w11 = W[(size_t)(k0 + 9) * HD + nn];

        uint4 v;
        uint32_t lo0, lo1;
        split2(w00, w01, v.x, lo0);
        split2(w10, w11, v.y, lo1);
        v.z = lo0;
        v.w = lo1;
        g_Bfrag[idx] = v;
    } else {
        int hb = b - TILES - PREPB_BLKS;
        int E4 = E >> 2;
        for (int i = hb * 256 + tid; i < E4; i += HIST_BLKS * 256) {
            int4 d = ((const int4*)dst)[i];
            atomicAdd(&g_cnt[d.x], 1);
            atomicAdd(&g_cnt[d.y], 1);
            atomicAdd(&g_cnt[d.z], 1);
            atomicAdd(&g_cnt[d.w], 1);
        }
        int i = E4 * 4 + hb * 256 + tid;
        if (i < E) atomicAdd(&g_cnt[dst[i]], 1);
    }
}

// ---------------------------------------------------------------------------
// K2: scan (also re-zeroes g_cnt for the next graph replay)
// ---------------------------------------------------------------------------
#define SCAN_T 1024
__global__ void scan_kernel(int n) {
    __shared__ int ssum[SCAN_T];
    const int tid = threadIdx.x;
    const int per = (n + SCAN_T - 1) / SCAN_T;
    const int start = tid * per;
    const int end   = min(start + per, n);

    int s = 0;
    for (int i = start; i < end; i++) s += g_cnt[i];
    ssum[tid] = s;
    __syncthreads();

    for (int off = 1; off < SCAN_T; off <<= 1) {
        int t = (tid >= off) ? ssum[tid - off] : 0;
        __syncthreads();
        ssum[tid] += t;
        __syncthreads();
    }

    int run = ssum[tid] - s;
    for (int i = start; i < end; i++) {
        int c = g_cnt[i];
        g_off[i] = run;
        g_pos[i] = run;
        g_cnt[i] = 0;        // restore invariant
        run += c;
    }
    if (tid == SCAN_T - 1) g_off[n] = run;
}

// ---------------------------------------------------------------------------
// K3: scatter — standalone, unconstrained occupancy (atomic-latency-bound,
// needs many warps in flight; fusing it under a reg-heavy kernel's
// launch_bounds throttled it ~3.5x).
// ---------------------------------------------------------------------------
__global__ void scatter_kernel(const int* __restrict__ src,
                               const int* __restrict__ dst, int E) {
    for (int i = blockIdx.x * blockDim.x + threadIdx.x; i < E;
         i += gridDim.x * blockDim.x) {
        int d = dst[i];
        int p = atomicAdd(&g_pos[d], 1);
        g_esrc[p] = src[i];
    }
}

// ---------------------------------------------------------------------------
// K4 (profiled slot): qkv_mma — 8 warps/block, 2 tiles/warp, B staged in
// 16KB smem per phase. Q epilogue pre-scales by QSCALE.
// ---------------------------------------------------------------------------
__global__ void __launch_bounds__(256, 2)
qkv_mma(const float* __restrict__ bq, const float* __restrict__ bk,
        const float* __restrict__ bv) {
    __shared__ uint4 sB[4 * 256];
    __shared__ float sbias[128];

    const int tid = threadIdx.x;
    const int wid  = tid >> 5;
    const int lane = tid & 31;
    const int m    = blockIdx.y;
    const int tile0 = blockIdx.x * 16 + wid * 2;

    const float* bias = (m == 0) ? bq : (m == 1) ? bk : bv;
    if (tid < 128) sbias[tid] = bias[tid];

    const uint4* Ah0 = &g_Afrag_hi[(size_t)tile0 * 256 + lane];
    const uint4* Al0 = &g_Afrag_lo[(size_t)tile0 * 256 + lane];
    const uint4* Ah1 = Ah0 + 256;
    const uint4* Al1 = Al0 + 256;

    const int r1 = tile0 * 16 + (lane >> 2);

#pragma unroll
    for (int jh = 0; jh < 2; jh++) {
        float acc[2][8][4];
#pragma unroll
        for (int t = 0; t < 2; t++)
#pragma unroll
            for (int j = 0; j < 8; j++)
#pragma unroll
                for (int r = 0; r < 4; r++) acc[t][j][r] = 0.f;

#pragma unroll
        for (int ph = 0; ph < 2; ph++) {
            __syncthreads();
#pragma unroll
            for (int i = 0; i < 4; i++) {
                int idx = tid + i * 256;
                int s4  = idx >> 8;
                int jj  = (idx >> 5) & 7;
                int ln  = idx & 31;
                sB[idx] = __ldg(&g_Bfrag[(size_t)((m * 8 + ph * 4 + s4) * 16 +
                                                  jh * 8 + jj) * 32 + ln]);
            }
            __syncthreads();

#pragma unroll
            for (int s4 = 0; s4 < 4; s4++) {
                const int s = ph * 4 + s4;
                const uint4 ah0 = Ah0[s * 32];
                const uint4 al0 = Al0[s * 32];
                const uint4 ah1 = Ah1[s * 32];
                const uint4 al1 = Al1[s * 32];
#pragma unroll
                for (int jj = 0; jj < 8; jj++) {
                    const uint4 b = sB[s4 * 256 + jj * 32 + lane];
                    MMA16816(acc[0][jj], ah0.x, ah0.y, ah0.z, ah0.w, b.x, b.y);
                    MMA16816(acc[0][jj], al0.x, al0.y, al0.z, al0.w, b.x, b.y);
                    MMA16816(acc[0][jj], ah0.x, ah0.y, ah0.z, ah0.w, b.z, b.w);
                    MMA16816(acc[1][jj], ah1.x, ah1.y, ah1.z, ah1.w, b.x, b.y);
                    MMA16816(acc[1][jj], al1.x, al1.y, al1.z, al1.w, b.x, b.y);
                    MMA16816(acc[1][jj], ah1.x, ah1.y, ah1.z, ah1.w, b.z, b.w);
                }
            }
        }

#pragma unroll
        for (int t = 0; t < 2; t++) {
            const int ra = r1 + t * 16;
            const int rb = ra + 8;
#pragma unroll
            for (int jj = 0; jj < 8; jj++) {
                const int c0 = (jh * 8 + jj) * 8 + (lane & 3) * 2;
                float o0 = acc[t][jj][0] + sbias[c0];
                float o1 = acc[t][jj][1] + sbias[c0 + 1];
                float o2 = acc[t][jj][2] + sbias[c0];
                float o3 = acc[t][jj][3] + sbias[c0 + 1];

                if (m == 0) {
                    o0 *= QSCALE; o1 *= QSCALE; o2 *= QSCALE; o3 *= QSCALE;
                    *(float2*)&g_Q[(size_t)ra * HD + c0] = make_float2(o0, o1);
                    *(float2*)&g_Q[(size_t)rb * HD + c0] = make_float2(o2, o3);
                } else {
                    const int kvlane = c0 >> 2;
                    const int pi     = (c0 >> 1) & 1;
                    const int ci     = (m == 1) ? pi : 2 + pi;
                    __half2 p1 = __floats2half2_rn(o0, o1);
                    __half2 p2 = __floats2half2_rn(o2, o3);
                    ((uint32_t*)&g_KV[(size_t)ra * 32 + kvlane])[ci] = *(uint32_t*)&p1;
                    ((uint32_t*)&g_KV[(size_t)rb * 32 + kvlane])[ci] = *(uint32_t*)&p2;
                }
            }
        }
    }
}

// ---------------------------------------------------------------------------
// K5: gather. Q pre-scaled, so score = ex2(clamp(p, +-PCLAMP)).
// fp32 V accumulation (known-good precision).
// ---------------------------------------------------------------------------
__global__ void gather_kernel(float* __restrict__ out, int n) {
    int node = (blockIdx.x * blockDim.x + threadIdx.x) >> 5;
    if (node >= n) return;
    const int lane = threadIdx.x & 31;

    const float4 q4 = *(const float4*)&g_Q[(size_t)node * HD + lane * 4];

    float ax = 0.f, ay = 0.f, az = 0.f, aw = 0.f;
    float zacc = 0.f;

    const int beg  = g_off[node];
    const int endo = g_off[node + 1];

    for (int ebase = beg; ebase < endo; ebase += 32) {
        int eidx = ebase + lane;
        int my_s = (eidx < endo) ? g_esrc[eidx] : 0;
        int cnt = endo - ebase;
        if (cnt > 32) cnt = 32;

        int j = 0;
        for (; j + 8 <= cnt; j += 8) {
            uint4 kv[8];
#pragma unroll
            for (int u = 0; u < 8; u++) {
                int s = __shfl_sync(0xffffffffu, my_s, j + u);
                kv[u] = g_KV[(size_t)s * 32 + lane];
            }
#pragma unroll
            for (int u = 0; u < 8; u++) {
                float2 k01 = __half22float2(*reinterpret_cast<__half2*>(&kv[u].x));
                float2 k23 = __half22float2(*reinterpret_cast<__half2*>(&kv[u].y));

                float p = k01.x * q4.x + k01.y * q4.y + k23.x * q4.z + k23.y * q4.w;
                p += __shfl_xor_sync(0xffffffffu, p, 1);
                p += __shfl_xor_sync(0xffffffffu, p, 2);

                p = fminf(fmaxf(p, -PCLAMP), PCLAMP);
                float sc;
                asm("ex2.approx.f32 %0, %1;" : "=f"(sc) : "f"(p));

                float2 v01 = __half22float2(*reinterpret_cast<__half2*>(&kv[u].z));
                float2 v23 = __half22float2(*reinterpret_cast<__half2*>(&kv[u].w));

                ax += v01.x * sc;
                ay += v01.y * sc;
                az += v23.x * sc;
                aw += v23.y * sc;
                zacc += sc;
            }
        }
        for (; j < cnt; j++) {
            int s = __shfl_sync(0xffffffffu, my_s, j);
            uint4 kv = g_KV[(size_t)s * 32 + lane];

            float2 k01 = __half22float2(*reinterpret_cast<__half2*>(&kv.x));
            float2 k23 = __half22float2(*reinterpret_cast<__half2*>(&kv.y));

            float p = k01.x * q4.x + k01.y * q4.y + k23.x * q4.z + k23.y * q4.w;
            p += __shfl_xor_sync(0xffffffffu, p, 1);
            p += __shfl_xor_sync(0xffffffffu, p, 2);

            p = fminf(fmaxf(p, -PCLAMP), PCLAMP);
            float sc;
            asm("ex2.approx.f32 %0, %1;" : "=f"(sc) : "f"(p));

            float2 v01 = __half22float2(*reinterpret_cast<__half2*>(&kv.z));
            float2 v23 = __half22float2(*reinterpret_cast<__half2*>(&kv.w));

            ax += v01.x * sc;
            ay += v01.y * sc;
            az += v23.x * sc;
            aw += v23.y * sc;
            zacc += sc;
        }
    }

    float inv = 1.0f / (zacc + 1e-6f);
    float4 o = make_float4(ax * inv, ay * inv, az * inv, aw * inv);
    *(float4*)&out[(size_t)node * HD + lane * 4] = o;
}

// ---------------------------------------------------------------------------
extern "C" void kernel_launch(void* const* d_in, const int* in_sizes, int n_in,
                              void* d_out, int out_size) {
    const float* h  = (const float*)d_in[0];
    const float* Wq = (const float*)d_in[1];
    const float* bq = (const float*)d_in[2];
    const float* Wk = (const float*)d_in[3];
    const float* bk = (const float*)d_in[4];
    const float* Wv = (const float*)d_in[5];
    const float* bv = (const float*)d_in[6];
    const int*  src = (const int*)d_in[7];
    const int*  dst = (const int*)d_in[8];
    float* out = (float*)d_out;

    const int n = in_sizes[0] / HD;
    const int E = in_sizes[7];

    // 5 launches: #1 prep+hist, #2 scan, #3 scatter (full occupancy),
    // #4 qkv_mma (profiled slot), #5 gather
    prep_hist_kernel<<<TILES + PREPB_BLKS + HIST_BLKS, 256>>>(h, Wq, Wk, Wv, dst, n, E);
    scan_kernel<<<1, SCAN_T>>>(n);
    scatter_kernel<<<2368, 256>>>(src, dst, E);
    dim3 gg(MMA_BLKS, 3);
    qkv_mma<<<gg, 256>>>(bq, bk, bv);
    gather_kernel<<<(n * 32 + 255) / 256, 256>>>(out, n);
}

// round 16
// speedup vs baseline: 1.5463x; 1.5463x over previous
#include <cuda_runtime.h>
#include <cuda_bf16.h>
#include <cuda_fp16.h>
#include <math.h>
#include <cstdint>

#define HD       128
#define MAXN     50000
#define MAXN_PAD 50176            // 3136 * 16
#define MAXE     1600000
#define TILES    (MAXN_PAD / 16)  // 3136
#define KSTEPS   8

#define PREPB_THREADS (3 * KSTEPS * 16 * 32)   // 12288
#define PREPB_BLKS    (PREPB_THREADS / 256)    // 48
#define HIST_BLKS     1184
#define MMA_BLKS      (TILES / 16)             // 196
#define SCAN_BLKS     49                       // ceil(50000/1024)

// Q pre-scale: 0.25 * log2(e); clamp bound: 5 * log2(e)
#define QSCALE 0.36067376022224085f
#define PCLAMP 7.213475204444817f

// ---------------------------------------------------------------------------
// Device scratch (allocation-free; zero-initialized at module load)
// ---------------------------------------------------------------------------
__device__ float g_Q[MAXN_PAD * HD];
// Interleaved K/V, fp16: g_KV[node*32 + l] = {K2(4l),K2(4l+2),V2(4l),V2(4l+2)}
__device__ uint4 g_KV[MAXN_PAD * 32];

__device__ uint4 g_Afrag_hi[TILES * KSTEPS * 32];
__device__ uint4 g_Afrag_lo[TILES * KSTEPS * 32];
__device__ uint4 g_Bfrag[3 * KSTEPS * 16 * 32];

// CSR sort scratch. g_cnt starts zero (module init) and is re-zeroed by
// scan2_kernel each call, keeping the graph-replay invariant.
__device__ int g_cnt[MAXN];
__device__ int g_off[MAXN + 1];
__device__ int g_pos[MAXN];
__device__ int g_esrc[MAXE];
// two-phase scan staging
__device__ int g_sloc[SCAN_BLKS * 1024];
__device__ int g_bsum[SCAN_BLKS];

// ---------------------------------------------------------------------------
// Helpers
// ---------------------------------------------------------------------------
__device__ __forceinline__ void split2(float x, float y, uint32_t& hi, uint32_t& lo) {
    __nv_bfloat16 hx = __float2bfloat16(x);
    __nv_bfloat16 hy = __float2bfloat16(y);
    __nv_bfloat16 lx = __float2bfloat16(x - __bfloat162float(hx));
    __nv_bfloat16 ly = __float2bfloat16(y - __bfloat162float(hy));
    __nv_bfloat162 H(hx, hy), L(lx, ly);
    hi = *(uint32_t*)&H;
    lo = *(uint32_t*)&L;
}

#define MMA16816(c, a0, a1, a2, a3, b0, b1)                                  \
    asm volatile(                                                            \
        "mma.sync.aligned.m16n8k16.row.col.f32.bf16.bf16.f32 "              \
        "{%0,%1,%2,%3}, {%4,%5,%6,%7}, {%8,%9}, {%0,%1,%2,%3};"             \
        : "+f"((c)[0]), "+f"((c)[1]), "+f"((c)[2]), "+f"((c)[3])             \
        : "r"(a0), "r"(a1), "r"(a2), "r"(a3), "r"(b0), "r"(b1))

// ---------------------------------------------------------------------------
// K1: prep_A + prep_B + hist (independent block ranges)
// ---------------------------------------------------------------------------
__global__ void prep_hist_kernel(const float* __restrict__ h,
                                 const float* __restrict__ Wq,
                                 const float* __restrict__ Wk,
                                 const float* __restrict__ Wv,
                                 const int* __restrict__ dst,
                                 int n, int E) {
    const int b = blockIdx.x;
    const int tid = threadIdx.x;

    if (b < TILES) {
        int idx = b * 256 + tid;
        int lane = idx & 31;
        int s    = (idx >> 5) & 7;
        int t    = b;

        int r1 = t * 16 + (lane >> 2);
        int r2 = r1 + 8;
        int c0 = s * 16 + (lane & 3) * 2;

        float2 x00 = make_float2(0.f, 0.f), x10 = x00, x01 = x00, x11 = x00;
        if (r1 < n) {
            x00 = *(const float2*)&h[(size_t)r1 * HD + c0];
            x01 = *(const float2*)&h[(size_t)r1 * HD + c0 + 8];
        }
        if (r2 < n) {
            x10 = *(const float2*)&h[(size_t)r2 * HD + c0];
            x11 = *(const float2*)&h[(size_t)r2 * HD + c0 + 8];
        }

        uint4 hi, lo;
        split2(x00.x, x00.y, hi.x, lo.x);
        split2(x10.x, x10.y, hi.y, lo.y);
        split2(x01.x, x01.y, hi.z, lo.z);
        split2(x11.x, x11.y, hi.w, lo.w);

        g_Afrag_hi[idx] = hi;
        g_Afrag_lo[idx] = lo;
    } else if (b < TILES + PREPB_BLKS) {
        int idx = (b - TILES) * 256 + tid;
        int lane = idx & 31;
        int j    = (idx >> 5) & 15;
        int s    = (idx >> 9) & 7;
        int m    = idx >> 12;

        const float* W = (m == 0) ? Wq : (m == 1) ? Wk : Wv;
        int nn = j * 8 + (lane >> 2);
        int k0 = s * 16 + (lane & 3) * 2;

        float w00 = W[(size_t)(k0 + 0) * HD + nn];
        float w01 = W[(size_t)(k0 + 1) * HD + nn];
        float w10 = W[(size_t)(k0 + 8) * HD + nn];
        float w11 = W[(size_t)(k0 + 9) * HD + nn];

        uint4 v;
        uint32_t lo0, lo1;
        split2(w00, w01, v.x, lo0);
        split2(w10, w11, v.y, lo1);
        v.z = lo0;
        v.w = lo1;
        g_Bfrag[idx] = v;
    } else {
        int hb = b - TILES - PREPB_BLKS;
        int E4 = E >> 2;
        for (int i = hb * 256 + tid; i < E4; i += HIST_BLKS * 256) {
            int4 d = ((const int4*)dst)[i];
            atomicAdd(&g_cnt[d.x], 1);
            atomicAdd(&g_cnt[d.y], 1);
            atomicAdd(&g_cnt[d.z], 1);
            atomicAdd(&g_cnt[d.w], 1);
        }
        int i = E4 * 4 + hb * 256 + tid;
        if (i < E) atomicAdd(&g_cnt[dst[i]], 1);
    }
}

// ---------------------------------------------------------------------------
// K2a: scan phase 1 — coalesced per-block Hillis-Steele; local exclusive
// scan to g_sloc, block totals to g_bsum.
// ---------------------------------------------------------------------------
__global__ void scan1_kernel(int n) {
    __shared__ int sh[1024];
    const int b = blockIdx.x, tid = threadIdx.x;
    const int i = b * 1024 + tid;

    int v = (i < n) ? g_cnt[i] : 0;
    sh[tid] = v;
    __syncthreads();

#pragma unroll
    for (int off = 1; off < 1024; off <<= 1) {
        int t = (tid >= off) ? sh[tid - off] : 0;
        __syncthreads();
        sh[tid] += t;
        __syncthreads();
    }

    g_sloc[i] = sh[tid] - v;                 // local exclusive
    if (tid == 1023) g_bsum[b] = sh[1023];   // block total
}

// ---------------------------------------------------------------------------
// K2b: scan phase 2 — add block-offset prefix, emit g_off/g_pos, re-zero
// g_cnt, write g_off[n].
// ---------------------------------------------------------------------------
__global__ void scan2_kernel(int n) {
    __shared__ int s_off;
    const int b = blockIdx.x, tid = threadIdx.x;

    if (tid == 0) {
        int o = 0;
        for (int k = 0; k < b; k++) o += g_bsum[k];
        s_off = o;
        if (b == gridDim.x - 1) {
            int tot = o;
            for (int k = b; k < (int)gridDim.x; k++) tot += g_bsum[k];
            g_off[n] = tot;
        }
    }
    __syncthreads();

    const int i = b * 1024 + tid;
    if (i < n) {
        int val = g_sloc[i] + s_off;
        g_off[i] = val;
        g_pos[i] = val;
        g_cnt[i] = 0;        // restore invariant for next graph replay
    }
}

// ---------------------------------------------------------------------------
// K3 (launch #4, profiled): qkv_mma — 8 warps/block, 2 tiles/warp, B staged
// in 16KB smem per phase. Q epilogue pre-scales by QSCALE.
// ---------------------------------------------------------------------------
__global__ void __launch_bounds__(256, 2)
qkv_mma(const float* __restrict__ bq, const float* __restrict__ bk,
        const float* __restrict__ bv) {
    __shared__ uint4 sB[4 * 256];
    __shared__ float sbias[128];

    const int tid = threadIdx.x;
    const int wid  = tid >> 5;
    const int lane = tid & 31;
    const int m    = blockIdx.y;
    const int tile0 = blockIdx.x * 16 + wid * 2;

    const float* bias = (m == 0) ? bq : (m == 1) ? bk : bv;
    if (tid < 128) sbias[tid] = bias[tid];

    const uint4* Ah0 = &g_Afrag_hi[(size_t)tile0 * 256 + lane];
    const uint4* Al0 = &g_Afrag_lo[(size_t)tile0 * 256 + lane];
    const uint4* Ah1 = Ah0 + 256;
    const uint4* Al1 = Al0 + 256;

    const int r1 = tile0 * 16 + (lane >> 2);

#pragma unroll
    for (int jh = 0; jh < 2; jh++) {
        float acc[2][8][4];
#pragma unroll
        for (int t = 0; t < 2; t++)
#pragma unroll
            for (int j = 0; j < 8; j++)
#pragma unroll
                for (int r = 0; r < 4; r++) acc[t][j][r] = 0.f;

#pragma unroll
        for (int ph = 0; ph < 2; ph++) {
            __syncthreads();
#pragma unroll
            for (int i = 0; i < 4; i++) {
                int idx = tid + i * 256;
                int s4  = idx >> 8;
                int jj  = (idx >> 5) & 7;
                int ln  = idx & 31;
                sB[idx] = __ldg(&g_Bfrag[(size_t)((m * 8 + ph * 4 + s4) * 16 +
                                                  jh * 8 + jj) * 32 + ln]);
            }
            __syncthreads();

#pragma unroll
            for (int s4 = 0; s4 < 4; s4++) {
                const int s = ph * 4 + s4;
                const uint4 ah0 = Ah0[s * 32];
                const uint4 al0 = Al0[s * 32];
                const uint4 ah1 = Ah1[s * 32];
                const uint4 al1 = Al1[s * 32];
#pragma unroll
                for (int jj = 0; jj < 8; jj++) {
                    const uint4 b = sB[s4 * 256 + jj * 32 + lane];
                    MMA16816(acc[0][jj], ah0.x, ah0.y, ah0.z, ah0.w, b.x, b.y);
                    MMA16816(acc[0][jj], al0.x, al0.y, al0.z, al0.w, b.x, b.y);
                    MMA16816(acc[0][jj], ah0.x, ah0.y, ah0.z, ah0.w, b.z, b.w);
                    MMA16816(acc[1][jj], ah1.x, ah1.y, ah1.z, ah1.w, b.x, b.y);
                    MMA16816(acc[1][jj], al1.x, al1.y, al1.z, al1.w, b.x, b.y);
                    MMA16816(acc[1][jj], ah1.x, ah1.y, ah1.z, ah1.w, b.z, b.w);
                }
            }
        }

#pragma unroll
        for (int t = 0; t < 2; t++) {
            const int ra = r1 + t * 16;
            const int rb = ra + 8;
#pragma unroll
            for (int jj = 0; jj < 8; jj++) {
                const int c0 = (jh * 8 + jj) * 8 + (lane & 3) * 2;
                float o0 = acc[t][jj][0] + sbias[c0];
                float o1 = acc[t][jj][1] + sbias[c0 + 1];
                float o2 = acc[t][jj][2] + sbias[c0];
                float o3 = acc[t][jj][3] + sbias[c0 + 1];

                if (m == 0) {
                    o0 *= QSCALE; o1 *= QSCALE; o2 *= QSCALE; o3 *= QSCALE;
                    *(float2*)&g_Q[(size_t)ra * HD + c0] = make_float2(o0, o1);
                    *(float2*)&g_Q[(size_t)rb * HD + c0] = make_float2(o2, o3);
                } else {
                    const int kvlane = c0 >> 2;
                    const int pi     = (c0 >> 1) & 1;
                    const int ci     = (m == 1) ? pi : 2 + pi;
                    __half2 p1 = __floats2half2_rn(o0, o1);
                    __half2 p2 = __floats2half2_rn(o2, o3);
                    ((uint32_t*)&g_KV[(size_t)ra * 32 + kvlane])[ci] = *(uint32_t*)&p1;
                    ((uint32_t*)&g_KV[(size_t)rb * 32 + kvlane])[ci] = *(uint32_t*)&p2;
                }
            }
        }
    }
}

// ---------------------------------------------------------------------------
// K4: scatter — standalone, unconstrained occupancy
// ---------------------------------------------------------------------------
__global__ void scatter_kernel(const int* __restrict__ src,
                               const int* __restrict__ dst, int E) {
    for (int i = blockIdx.x * blockDim.x + threadIdx.x; i < E;
         i += gridDim.x * blockDim.x) {
        int d = dst[i];
        int p = atomicAdd(&g_pos[d], 1);
        g_esrc[p] = src[i];
    }
}

// ---------------------------------------------------------------------------
// K5: gather. Q pre-scaled, so score = ex2(clamp(p, +-PCLAMP)).
// fp32 V accumulation (known-good precision).
// ---------------------------------------------------------------------------
__global__ void gather_kernel(float* __restrict__ out, int n) {
    int node = (blockIdx.x * blockDim.x + threadIdx.x) >> 5;
    if (node >= n) return;
    const int lane = threadIdx.x & 31;

    const float4 q4 = *(const float4*)&g_Q[(size_t)node * HD + lane * 4];

    float ax = 0.f, ay = 0.f, az = 0.f, aw = 0.f;
    float zacc = 0.f;

    const int beg  = g_off[node];
    const int endo = g_off[node + 1];

    for (int ebase = beg; ebase < endo; ebase += 32) {
        int eidx = ebase + lane;
        int my_s = (eidx < endo) ? g_esrc[eidx] : 0;
        int cnt = endo - ebase;
        if (cnt > 32) cnt = 32;

        int j = 0;
        for (; j + 8 <= cnt; j += 8) {
            uint4 kv[8];
#pragma unroll
            for (int u = 0; u < 8; u++) {
                int s = __shfl_sync(0xffffffffu, my_s, j + u);
                kv[u] = g_KV[(size_t)s * 32 + lane];
            }
#pragma unroll
            for (int u = 0; u < 8; u++) {
                float2 k01 = __half22float2(*reinterpret_cast<__half2*>(&kv[u].x));
                float2 k23 = __half22float2(*reinterpret_cast<__half2*>(&kv[u].y));

                float p = k01.x * q4.x + k01.y * q4.y + k23.x * q4.z + k23.y * q4.w;
                p += __shfl_xor_sync(0xffffffffu, p, 1);
                p += __shfl_xor_sync(0xffffffffu, p, 2);

                p = fminf(fmaxf(p, -PCLAMP), PCLAMP);
                float sc;
                asm("ex2.approx.f32 %0, %1;" : "=f"(sc) : "f"(p));

                float2 v01 = __half22float2(*reinterpret_cast<__half2*>(&kv[u].z));
                float2 v23 = __half22float2(*reinterpret_cast<__half2*>(&kv[u].w));

                ax += v01.x * sc;
                ay += v01.y * sc;
                az += v23.x * sc;
                aw += v23.y * sc;
                zacc += sc;
            }
        }
        for (; j < cnt; j++) {
            int s = __shfl_sync(0xffffffffu, my_s, j);
            uint4 kv = g_KV[(size_t)s * 32 + lane];

            float2 k01 = __half22float2(*reinterpret_cast<__half2*>(&kv.x));
            float2 k23 = __half22float2(*reinterpret_cast<__half2*>(&kv.y));

            float p = k01.x * q4.x + k01.y * q4.y + k23.x * q4.z + k23.y * q4.w;
            p += __shfl_xor_sync(0xffffffffu, p, 1);
            p += __shfl_xor_sync(0xffffffffu, p, 2);

            p = fminf(fmaxf(p, -PCLAMP), PCLAMP);
            float sc;
            asm("ex2.approx.f32 %0, %1;" : "=f"(sc) : "f"(p));

            float2 v01 = __half22float2(*reinterpret_cast<__half2*>(&kv.z));
            float2 v23 = __half22float2(*reinterpret_cast<__half2*>(&kv.w));

            ax += v01.x * sc;
            ay += v01.y * sc;
            az += v23.x * sc;
            aw += v23.y * sc;
            zacc += sc;
        }
    }

    float inv = 1.0f / (zacc + 1e-6f);
    float4 o = make_float4(ax * inv, ay * inv, az * inv, aw * inv);
    *(float4*)&out[(size_t)node * HD + lane * 4] = o;
}

// ---------------------------------------------------------------------------
extern "C" void kernel_launch(void* const* d_in, const int* in_sizes, int n_in,
                              void* d_out, int out_size) {
    const float* h  = (const float*)d_in[0];
    const float* Wq = (const float*)d_in[1];
    const float* bq = (const float*)d_in[2];
    const float* Wk = (const float*)d_in[3];
    const float* bk = (const float*)d_in[4];
    const float* Wv = (const float*)d_in[5];
    const float* bv = (const float*)d_in[6];
    const int*  src = (const int*)d_in[7];
    const int*  dst = (const int*)d_in[8];
    float* out = (float*)d_out;

    const int n = in_sizes[0] / HD;
    const int E = in_sizes[7];

    // 6 launches: #1 prep+hist, #2 scan1, #3 scan2, #4 qkv_mma (profiled),
    // #5 scatter, #6 gather
    prep_hist_kernel<<<TILES + PREPB_BLKS + HIST_BLKS, 256>>>(h, Wq, Wk, Wv, dst, n, E);
    scan1_kernel<<<SCAN_BLKS, 1024>>>(n);
    scan2_kernel<<<SCAN_BLKS, 1024>>>(n);
    dim3 gg(MMA_BLKS, 3);
    qkv_mma<<<gg, 256>>>(bq, bk, bv);
    scatter_kernel<<<2368, 256>>>(src, dst, E);
    gather_kernel<<<(n * 32 + 255) / 256, 256>>>(out, n);
}

// round 17
// speedup vs baseline: 1.6571x; 1.0716x over previous
#include <cuda_runtime.h>
#include <cuda_bf16.h>
#include <cuda_fp16.h>
#include <math.h>
#include <cstdint>

#define HD       128
#define MAXN     50000
#define MAXN_PAD 50176            // 3136 * 16
#define MAXE     1600000
#define TILES    (MAXN_PAD / 16)  // 3136
#define KSTEPS   8

#define PREPB_THREADS (3 * KSTEPS * 16 * 32)   // 12288
#define PREPB_BLKS    (PREPB_THREADS / 256)    // 48
#define HIST_BLKS     1184
#define MMA_BLKS      (TILES / 16)             // 196
#define SCAN_BLKS     49                       // ceil(50000/1024)

// Q pre-scale: 0.25 * log2(e); clamp bound: 5 * log2(e)
#define QSCALE 0.36067376022224085f
#define PCLAMP 7.213475204444817f

// ---------------------------------------------------------------------------
// Device scratch (allocation-free; zero-initialized at module load)
// ---------------------------------------------------------------------------
__device__ float g_Q[MAXN_PAD * HD];
// Interleaved K/V, fp16: g_KV[node*32 + l] = {K2(4l),K2(4l+2),V2(4l),V2(4l+2)}
__device__ uint4 g_KV[MAXN_PAD * 32];

__device__ uint4 g_Afrag_hi[TILES * KSTEPS * 32];
__device__ uint4 g_Afrag_lo[TILES * KSTEPS * 32];
__device__ uint4 g_Bfrag[3 * KSTEPS * 16 * 32];

// CSR sort scratch. g_cnt starts zero (module init) and is re-zeroed by
// scan2_kernel each call, keeping the graph-replay invariant.
__device__ int g_cnt[MAXN];
__device__ int g_off[MAXN + 1];
__device__ int g_pos[MAXN];
__device__ int g_esrc[MAXE];
// two-phase scan staging
__device__ int g_sloc[SCAN_BLKS * 1024];
__device__ int g_bsum[SCAN_BLKS];

// ---------------------------------------------------------------------------
// Helpers
// ---------------------------------------------------------------------------
__device__ __forceinline__ void split2(float x, float y, uint32_t& hi, uint32_t& lo) {
    __nv_bfloat16 hx = __float2bfloat16(x);
    __nv_bfloat16 hy = __float2bfloat16(y);
    __nv_bfloat16 lx = __float2bfloat16(x - __bfloat162float(hx));
    __nv_bfloat16 ly = __float2bfloat16(y - __bfloat162float(hy));
    __nv_bfloat162 H(hx, hy), L(lx, ly);
    hi = *(uint32_t*)&H;
    lo = *(uint32_t*)&L;
}

#define MMA16816(c, a0, a1, a2, a3, b0, b1)                                  \
    asm volatile(                                                            \
        "mma.sync.aligned.m16n8k16.row.col.f32.bf16.bf16.f32 "              \
        "{%0,%1,%2,%3}, {%4,%5,%6,%7}, {%8,%9}, {%0,%1,%2,%3};"             \
        : "+f"((c)[0]), "+f"((c)[1]), "+f"((c)[2]), "+f"((c)[3])             \
        : "r"(a0), "r"(a1), "r"(a2), "r"(a3), "r"(b0), "r"(b1))

// ---------------------------------------------------------------------------
// K1: prep_A + prep_B + hist (independent block ranges)
// ---------------------------------------------------------------------------
__global__ void prep_hist_kernel(const float* __restrict__ h,
                                 const float* __restrict__ Wq,
                                 const float* __restrict__ Wk,
                                 const float* __restrict__ Wv,
                                 const int* __restrict__ dst,
                                 int n, int E) {
    const int b = blockIdx.x;
    const int tid = threadIdx.x;

    if (b < TILES) {
        int idx = b * 256 + tid;
        int lane = idx & 31;
        int s    = (idx >> 5) & 7;
        int t    = b;

        int r1 = t * 16 + (lane >> 2);
        int r2 = r1 + 8;
        int c0 = s * 16 + (lane & 3) * 2;

        float2 x00 = make_float2(0.f, 0.f), x10 = x00, x01 = x00, x11 = x00;
        if (r1 < n) {
            x00 = *(const float2*)&h[(size_t)r1 * HD + c0];
            x01 = *(const float2*)&h[(size_t)r1 * HD + c0 + 8];
        }
        if (r2 < n) {
            x10 = *(const float2*)&h[(size_t)r2 * HD + c0];
            x11 = *(const float2*)&h[(size_t)r2 * HD + c0 + 8];
        }

        uint4 hi, lo;
        split2(x00.x, x00.y, hi.x, lo.x);
        split2(x10.x, x10.y, hi.y, lo.y);
        split2(x01.x, x01.y, hi.z, lo.z);
        split2(x11.x, x11.y, hi.w, lo.w);

        g_Afrag_hi[idx] = hi;
        g_Afrag_lo[idx] = lo;
    } else if (b < TILES + PREPB_BLKS) {
        int idx = (b - TILES) * 256 + tid;
        int lane = idx & 31;
        int j    = (idx >> 5) & 15;
        int s    = (idx >> 9) & 7;
        int m    = idx >> 12;

        const float* W = (m == 0) ? Wq : (m == 1) ? Wk : Wv;
        int nn = j * 8 + (lane >> 2);
        int k0 = s * 16 + (lane & 3) * 2;

        float w00 = W[(size_t)(k0 + 0) * HD + nn];
        float w01 = W[(size_t)(k0 + 1) * HD + nn];
        float w10 = W[(size_t)(k0 + 8) * HD + nn];
        float w11 = W[(size_t)(k0 + 9) * HD + nn];

        uint4 v;
        uint32_t lo0, lo1;
        split2(w00, w01, v.x, lo0);
        split2(w10, w11, v.y, lo1);
        v.z = lo0;
        v.w = lo1;
        g_Bfrag[idx] = v;
    } else {
        int hb = b - TILES - PREPB_BLKS;
        int E4 = E >> 2;
        for (int i = hb * 256 + tid; i < E4; i += HIST_BLKS * 256) {
            int4 d = ((const int4*)dst)[i];
            atomicAdd(&g_cnt[d.x], 1);
            atomicAdd(&g_cnt[d.y], 1);
            atomicAdd(&g_cnt[d.z], 1);
            atomicAdd(&g_cnt[d.w], 1);
        }
        int i = E4 * 4 + hb * 256 + tid;
        if (i < E) atomicAdd(&g_cnt[dst[i]], 1);
    }
}

// ---------------------------------------------------------------------------
// K2a: scan phase 1 — coalesced per-block Hillis-Steele
// ---------------------------------------------------------------------------
__global__ void scan1_kernel(int n) {
    __shared__ int sh[1024];
    const int b = blockIdx.x, tid = threadIdx.x;
    const int i = b * 1024 + tid;

    int v = (i < n) ? g_cnt[i] : 0;
    sh[tid] = v;
    __syncthreads();

#pragma unroll
    for (int off = 1; off < 1024; off <<= 1) {
        int t = (tid >= off) ? sh[tid - off] : 0;
        __syncthreads();
        sh[tid] += t;
        __syncthreads();
    }

    g_sloc[i] = sh[tid] - v;
    if (tid == 1023) g_bsum[b] = sh[1023];
}

// ---------------------------------------------------------------------------
// K2b: scan phase 2 — add block prefix, emit g_off/g_pos, re-zero g_cnt
// ---------------------------------------------------------------------------
__global__ void scan2_kernel(int n) {
    __shared__ int s_off;
    const int b = blockIdx.x, tid = threadIdx.x;

    if (tid == 0) {
        int o = 0;
        for (int k = 0; k < b; k++) o += g_bsum[k];
        s_off = o;
        if (b == gridDim.x - 1) {
            int tot = o;
            for (int k = b; k < (int)gridDim.x; k++) tot += g_bsum[k];
            g_off[n] = tot;
        }
    }
    __syncthreads();

    const int i = b * 1024 + tid;
    if (i < n) {
        int val = g_sloc[i] + s_off;
        g_off[i] = val;
        g_pos[i] = val;
        g_cnt[i] = 0;
    }
}

// ---------------------------------------------------------------------------
// qkv_mma — 8 warps/block, 2 tiles/warp, B staged in 16KB smem per phase.
// Runs on a SIDE STREAM concurrent with scan/scatter (disjoint pipes).
// ---------------------------------------------------------------------------
__global__ void __launch_bounds__(256, 2)
qkv_mma(const float* __restrict__ bq, const float* __restrict__ bk,
        const float* __restrict__ bv) {
    __shared__ uint4 sB[4 * 256];
    __shared__ float sbias[128];

    const int tid = threadIdx.x;
    const int wid  = tid >> 5;
    const int lane = tid & 31;
    const int m    = blockIdx.y;
    const int tile0 = blockIdx.x * 16 + wid * 2;

    const float* bias = (m == 0) ? bq : (m == 1) ? bk : bv;
    if (tid < 128) sbias[tid] = bias[tid];

    const uint4* Ah0 = &g_Afrag_hi[(size_t)tile0 * 256 + lane];
    const uint4* Al0 = &g_Afrag_lo[(size_t)tile0 * 256 + lane];
    const uint4* Ah1 = Ah0 + 256;
    const uint4* Al1 = Al0 + 256;

    const int r1 = tile0 * 16 + (lane >> 2);

#pragma unroll
    for (int jh = 0; jh < 2; jh++) {
        float acc[2][8][4];
#pragma unroll
        for (int t = 0; t < 2; t++)
#pragma unroll
            for (int j = 0; j < 8; j++)
#pragma unroll
                for (int r = 0; r < 4; r++) acc[t][j][r] = 0.f;

#pragma unroll
        for (int ph = 0; ph < 2; ph++) {
            __syncthreads();
#pragma unroll
            for (int i = 0; i < 4; i++) {
                int idx = tid + i * 256;
                int s4  = idx >> 8;
                int jj  = (idx >> 5) & 7;
                int ln  = idx & 31;
                sB[idx] = __ldg(&g_Bfrag[(size_t)((m * 8 + ph * 4 + s4) * 16 +
                                                  jh * 8 + jj) * 32 + ln]);
            }
            __syncthreads();

#pragma unroll
            for (int s4 = 0; s4 < 4; s4++) {
                const int s = ph * 4 + s4;
                const uint4 ah0 = Ah0[s * 32];
                const uint4 al0 = Al0[s * 32];
                const uint4 ah1 = Ah1[s * 32];
                const uint4 al1 = Al1[s * 32];
#pragma unroll
                for (int jj = 0; jj < 8; jj++) {
                    const uint4 b = sB[s4 * 256 + jj * 32 + lane];
                    MMA16816(acc[0][jj], ah0.x, ah0.y, ah0.z, ah0.w, b.x, b.y);
                    MMA16816(acc[0][jj], al0.x, al0.y, al0.z, al0.w, b.x, b.y);
                    MMA16816(acc[0][jj], ah0.x, ah0.y, ah0.z, ah0.w, b.z, b.w);
                    MMA16816(acc[1][jj], ah1.x, ah1.y, ah1.z, ah1.w, b.x, b.y);
                    MMA16816(acc[1][jj], al1.x, al1.y, al1.z, al1.w, b.x, b.y);
                    MMA16816(acc[1][jj], ah1.x, ah1.y, ah1.z, ah1.w, b.z, b.w);
                }
            }
        }

#pragma unroll
        for (int t = 0; t < 2; t++) {
            const int ra = r1 + t * 16;
            const int rb = ra + 8;
#pragma unroll
            for (int jj = 0; jj < 8; jj++) {
                const int c0 = (jh * 8 + jj) * 8 + (lane & 3) * 2;
                float o0 = acc[t][jj][0] + sbias[c0];
                float o1 = acc[t][jj][1] + sbias[c0 + 1];
                float o2 = acc[t][jj][2] + sbias[c0];
                float o3 = acc[t][jj][3] + sbias[c0 + 1];

                if (m == 0) {
                    o0 *= QSCALE; o1 *= QSCALE; o2 *= QSCALE; o3 *= QSCALE;
                    *(float2*)&g_Q[(size_t)ra * HD + c0] = make_float2(o0, o1);
                    *(float2*)&g_Q[(size_t)rb * HD + c0] = make_float2(o2, o3);
                } else {
                    const int kvlane = c0 >> 2;
                    const int pi     = (c0 >> 1) & 1;
                    const int ci     = (m == 1) ? pi : 2 + pi;
                    __half2 p1 = __floats2half2_rn(o0, o1);
                    __half2 p2 = __floats2half2_rn(o2, o3);
                    ((uint32_t*)&g_KV[(size_t)ra * 32 + kvlane])[ci] = *(uint32_t*)&p1;
                    ((uint32_t*)&g_KV[(size_t)rb * 32 + kvlane])[ci] = *(uint32_t*)&p2;
                }
            }
        }
    }
}

// ---------------------------------------------------------------------------
// scatter — standalone, unconstrained occupancy
// ---------------------------------------------------------------------------
__global__ void scatter_kernel(const int* __restrict__ src,
                               const int* __restrict__ dst, int E) {
    for (int i = blockIdx.x * blockDim.x + threadIdx.x; i < E;
         i += gridDim.x * blockDim.x) {
        int d = dst[i];
        int p = atomicAdd(&g_pos[d], 1);
        g_esrc[p] = src[i];
    }
}

// ---------------------------------------------------------------------------
// gather: Q pre-scaled, score = ex2(clamp(p, +-PCLAMP)), fp32 V accumulation.
// ---------------------------------------------------------------------------
__global__ void gather_kernel(float* __restrict__ out, int n) {
    int node = (blockIdx.x * blockDim.x + threadIdx.x) >> 5;
    if (node >= n) return;
    const int lane = threadIdx.x & 31;

    const float4 q4 = *(const float4*)&g_Q[(size_t)node * HD + lane * 4];

    float ax = 0.f, ay = 0.f, az = 0.f, aw = 0.f;
    float zacc = 0.f;

    const int beg  = g_off[node];
    const int endo = g_off[node + 1];

    for (int ebase = beg; ebase < endo; ebase += 32) {
        int eidx = ebase + lane;
        int my_s = (eidx < endo) ? g_esrc[eidx] : 0;
        int cnt = endo - ebase;
        if (cnt > 32) cnt = 32;

        int j = 0;
        for (; j + 8 <= cnt; j += 8) {
            uint4 kv[8];
#pragma unroll
            for (int u = 0; u < 8; u++) {
                int s = __shfl_sync(0xffffffffu, my_s, j + u);
                kv[u] = g_KV[(size_t)s * 32 + lane];
            }
#pragma unroll
            for (int u = 0; u < 8; u++) {
                float2 k01 = __half22float2(*reinterpret_cast<__half2*>(&kv[u].x));
                float2 k23 = __half22float2(*reinterpret_cast<__half2*>(&kv[u].y));

                float p = k01.x * q4.x + k01.y * q4.y + k23.x * q4.z + k23.y * q4.w;
                p += __shfl_xor_sync(0xffffffffu, p, 1);
                p += __shfl_xor_sync(0xffffffffu, p, 2);

                p = fminf(fmaxf(p, -PCLAMP), PCLAMP);
                float sc;
                asm("ex2.approx.f32 %0, %1;" : "=f"(sc) : "f"(p));

                float2 v01 = __half22float2(*reinterpret_cast<__half2*>(&kv[u].z));
                float2 v23 = __half22float2(*reinterpret_cast<__half2*>(&kv[u].w));

                ax += v01.x * sc;
                ay += v01.y * sc;
                az += v23.x * sc;
                aw += v23.y * sc;
                zacc += sc;
            }
        }
        for (; j < cnt; j++) {
            int s = __shfl_sync(0xffffffffu, my_s, j);
            uint4 kv = g_KV[(size_t)s * 32 + lane];

            float2 k01 = __half22float2(*reinterpret_cast<__half2*>(&kv.x));
            float2 k23 = __half22float2(*reinterpret_cast<__half2*>(&kv.y));

            float p = k01.x * q4.x + k01.y * q4.y + k23.x * q4.z + k23.y * q4.w;
            p += __shfl_xor_sync(0xffffffffu, p, 1);
            p += __shfl_xor_sync(0xffffffffu, p, 2);

            p = fminf(fmaxf(p, -PCLAMP), PCLAMP);
            float sc;
            asm("ex2.approx.f32 %0, %1;" : "=f"(sc) : "f"(p));

            float2 v01 = __half22float2(*reinterpret_cast<__half2*>(&kv.z));
            float2 v23 = __half22float2(*reinterpret_cast<__half2*>(&kv.w));

            ax += v01.x * sc;
            ay += v01.y * sc;
            az += v23.x * sc;
            aw += v23.y * sc;
            zacc += sc;
        }
    }

    float inv = 1.0f / (zacc + 1e-6f);
    float4 o = make_float4(ax * inv, ay * inv, az * inv, aw * inv);
    *(float4*)&out[(size_t)node * HD + lane * 4] = o;
}

// ---------------------------------------------------------------------------
extern "C" void kernel_launch(void* const* d_in, const int* in_sizes, int n_in,
                              void* d_out, int out_size) {
    const float* h  = (const float*)d_in[0];
    const float* Wq = (const float*)d_in[1];
    const float* bq = (const float*)d_in[2];
    const float* Wk = (const float*)d_in[3];
    const float* bk = (const float*)d_in[4];
    const float* Wv = (const float*)d_in[5];
    const float* bv = (const float*)d_in[6];
    const int*  src = (const int*)d_in[7];
    const int*  dst = (const int*)d_in[8];
    float* out = (float*)d_out;

    const int n = in_sizes[0] / HD;
    const int E = in_sizes[7];

    // Fork/join: after K1, {scan1->scan2->scatter} (L2/atomic-bound) runs on
    // the captured stream while qkv_mma (tensor-bound) runs on a side stream.
    cudaStream_t s2;
    cudaStreamCreateWithFlags(&s2, cudaStreamNonBlocking);
    cudaEvent_t eFork, eJoin;
    cudaEventCreateWithFlags(&eFork, cudaEventDisableTiming);
    cudaEventCreateWithFlags(&eJoin, cudaEventDisableTiming);

    prep_hist_kernel<<<TILES + PREPB_BLKS + HIST_BLKS, 256>>>(h, Wq, Wk, Wv, dst, n, E);

    cudaEventRecord(eFork, 0);
    cudaStreamWaitEvent(s2, eFork, 0);
    dim3 gg(MMA_BLKS, 3);
    qkv_mma<<<gg, 256, 0, s2>>>(bq, bk, bv);
    cudaEventRecord(eJoin, s2);

    scan1_kernel<<<SCAN_BLKS, 1024>>>(n);
    scan2_kernel<<<SCAN_BLKS, 1024>>>(n);
    scatter_kernel<<<2368, 256>>>(src, dst, E);

    cudaStreamWaitEvent(0, eJoin, 0);
    gather_kernel<<<(n * 32 + 255) / 256, 256>>>(out, n);

    // Destroy only when not capturing (destroying a capturing stream is
    // illegal; the capture call leaks one stream + two events, harmless).
    cudaStreamCaptureStatus st = cudaStreamCaptureStatusNone;
    cudaStreamIsCapturing(0, &st);
    if (st == cudaStreamCaptureStatusNone) {
        cudaStreamDestroy(s2);
        cudaEventDestroy(eFork);
        cudaEventDestroy(eJoin);
    }
}